// round 12
// baseline (speedup 1.0000x reference)
#include <cuda_runtime.h>
#include <math.h>

#define BB   128
#define VV   128000
#define NV4  (VV/4)
#define TPB  1024
#define CAND_MAX 3968

// monotonic float -> ordered uint32
__device__ __forceinline__ unsigned f2ord(float f) {
    unsigned u = __float_as_uint(f);
    return (u & 0x80000000u) ? ~u : (u | 0x80000000u);
}
// inverse (floor decode); NaN-zone keys self-correct the bisection
__device__ __forceinline__ float ord2f_floor(unsigned o) {
    if (o <= 0x007FFFFFu) return -__int_as_float(0x7f800000); // -inf: take all
    return (o & 0x80000000u) ? __uint_as_float(o ^ 0x80000000u)
                             : __uint_as_float(~o);
}

__device__ float blk_excl_scan(float v, float* tmp) {
    __syncthreads();
    int lane = threadIdx.x & 31, w = threadIdx.x >> 5;
    float x = v;
    #pragma unroll
    for (int o = 1; o < 32; o <<= 1) {
        float y = __shfl_up_sync(0xffffffffu, x, o);
        if (lane >= o) x += y;
    }
    if (lane == 31) tmp[w] = x;
    __syncthreads();
    if (w == 0) {
        float s = tmp[lane];
        #pragma unroll
        for (int o = 1; o < 32; o <<= 1) {
            float y = __shfl_up_sync(0xffffffffu, s, o);
            if (lane >= o) s += y;
        }
        tmp[lane] = s;
    }
    __syncthreads();
    float pre = (w > 0) ? tmp[w - 1] : 0.0f;
    return pre + x - v;
}

__device__ float blk_reduce_sum(float v, float* tmp) {
    __syncthreads();
    int lane = threadIdx.x & 31, w = threadIdx.x >> 5;
    #pragma unroll
    for (int o = 16; o; o >>= 1) v += __shfl_xor_sync(0xffffffffu, v, o);
    if (lane == 0) tmp[w] = v;
    __syncthreads();
    if (w == 0) {
        float x = tmp[lane];
        #pragma unroll
        for (int o = 16; o; o >>= 1) x += __shfl_xor_sync(0xffffffffu, x, o);
        if (lane == 0) tmp[0] = x;
    }
    __syncthreads();
    return tmp[0];
}

__device__ float blk_reduce_max(float v, float* tmp) {
    __syncthreads();
    int lane = threadIdx.x & 31, w = threadIdx.x >> 5;
    #pragma unroll
    for (int o = 16; o; o >>= 1) v = fmaxf(v, __shfl_xor_sync(0xffffffffu, v, o));
    if (lane == 0) tmp[w] = v;
    __syncthreads();
    if (w == 0) {
        float x = tmp[lane];
        #pragma unroll
        for (int o = 16; o; o >>= 1) x = fmaxf(x, __shfl_xor_sync(0xffffffffu, x, o));
        if (lane == 0) tmp[0] = x;
    }
    __syncthreads();
    return tmp[0];
}

struct CrossRes { int bin; float above; bool found; };

template<int NBINS>
__device__ CrossRes find_crossing(const float* wgt, float target, float* scanTmp,
                                  int* sh_r, int* sh_b, float* sh_c) {
    __syncthreads();
    const int bpt = (NBINS + TPB - 1) / TPB;
    int t = threadIdx.x;
    float s = 0.f;
    #pragma unroll
    for (int j = 0; j < bpt; j++) {
        int r = t * bpt + j;
        if (r < NBINS) s += wgt[NBINS - 1 - r];
    }
    float P = blk_excl_scan(s, scanTmp);
    if (t == 0) *sh_r = 0x7fffffff;
    __syncthreads();
    float cum = P;
    #pragma unroll
    for (int j = 0; j < bpt; j++) {
        int r = t * bpt + j;
        if (r < NBINS) {
            float wv = wgt[NBINS - 1 - r];
            if (cum < target && cum + wv >= target) atomicMin(sh_r, r);
            cum += wv;
        }
    }
    __syncthreads();
    int fr = *sh_r;
    if (fr != 0x7fffffff) {
        cum = P;
        #pragma unroll
        for (int j = 0; j < bpt; j++) {
            int r = t * bpt + j;
            if (r < NBINS) {
                float wv = wgt[NBINS - 1 - r];
                if (r == fr) { *sh_b = NBINS - 1 - r; *sh_c = cum; }
                cum += wv;
            }
        }
    }
    __syncthreads();
    CrossRes res;
    res.found = (fr != 0x7fffffff);
    res.bin = res.found ? *sh_b : 0;
    res.above = res.found ? *sh_c : 0.f;
    return res;
}

// total of a hist, bins-only (no candidate pass)
template<int NBINS>
__device__ float hist_total(const float* wgt, float* redTmp) {
    __syncthreads();
    const int bpt = (NBINS + TPB - 1) / TPB;
    int t = threadIdx.x;
    float s = 0.f;
    #pragma unroll
    for (int j = 0; j < bpt; j++) {
        int r = t * bpt + j;
        if (r < NBINS) s += wgt[r];
    }
    return blk_reduce_sum(s, redTmp);
}

__global__ void __launch_bounds__(TPB, 1)
topk_topp_sample_kernel(const float* __restrict__ logits,
                        const int*   __restrict__ karr,
                        const float* __restrict__ parr,
                        const float* __restrict__ qarr,
                        float* __restrict__ out_ids,
                        float* __restrict__ out_probs)
{
    __shared__ float cand[CAND_MAX];      // 15.5 KB
    __shared__ int   candIdx[CAND_MAX];   // 15.5 KB
    __shared__ float histbuf[4096];       // 16 KB, aliased across all levels
    __shared__ float scanTmp[32];
    __shared__ float redTmp[32];
    __shared__ int   shr; __shared__ int shb; __shared__ float shc;
    __shared__ int   shn;
    __shared__ float argV[32]; __shared__ int argI[32];

    const int row = blockIdx.x;
    const int t = threadIdx.x;
    const int lane = t & 31, warp = t >> 5;
    const float* lg = logits + (long long)row * VV;
    const float* qr = qarr   + (long long)row * VV;
    float* pro = out_probs + (long long)row * VV;
    const int   k = karr[row];
    const float p = parr[row];

    const float4* lg4 = reinterpret_cast<const float4*>(lg);
    float4* pr4 = reinterpret_cast<float4*>(pro);

    // ---- Zero-fill probs first: pure stores overlap later reads ----
    {
        const float4 z4 = make_float4(0.f, 0.f, 0.f, 0.f);
        int i = t;
        #pragma unroll 4
        for (; i < NV4; i += TPB) pr4[i] = z4;
    }

    // ---- Phase A: ILP-4 compaction, warp-scan offsets, fused row max ----
    const float NEG = -__int_as_float(0x7f800000);   // -inf sentinel (never taken)
    unsigned loK = 0u, hiK = 0xFFFFFFFFu, fK = 0xC0000000u;  // f2ord(2.0f)
    int n = 0;
    float mx;
    for (int iter = 0; iter < 20; iter++) {
        if (t == 0) shn = 0;
        mx = -3.4e38f;
        __syncthreads();
        const float ffloor = ord2f_floor(fK);
        for (int base = 0; base < NV4; base += 4 * TPB) {
            int i0 = base + t, i1 = i0 + TPB, i2 = i1 + TPB, i3 = i2 + TPB;
            float4 v0 = (i0 < NV4) ? lg4[i0] : make_float4(NEG, NEG, NEG, NEG);
            float4 v1 = (i1 < NV4) ? lg4[i1] : make_float4(NEG, NEG, NEG, NEG);
            float4 v2 = (i2 < NV4) ? lg4[i2] : make_float4(NEG, NEG, NEG, NEG);
            float4 v3 = (i3 < NV4) ? lg4[i3] : make_float4(NEG, NEG, NEG, NEG);
            float xs[16] = { v0.x, v0.y, v0.z, v0.w,  v1.x, v1.y, v1.z, v1.w,
                             v2.x, v2.y, v2.z, v2.w,  v3.x, v3.y, v3.z, v3.w };
            unsigned pm = 0;   // 16-bit predicate mask
            int cnt = 0;
            #pragma unroll
            for (int j = 0; j < 16; j++) {
                bool tk = (xs[j] >= ffloor);
                pm |= (unsigned)tk << j;
                cnt += (int)tk;
                if (tk) mx = fmaxf(mx, xs[j]);
            }
            // warp inclusive scan of cnt
            int inc = cnt;
            #pragma unroll
            for (int o = 1; o < 32; o <<= 1) {
                int y = __shfl_up_sync(0xffffffffu, inc, o);
                if (lane >= o) inc += y;
            }
            int wtot = __shfl_sync(0xffffffffu, inc, 31);
            if (wtot) {
                int wbase = 0;
                if (lane == 31) wbase = atomicAdd(&shn, wtot);
                wbase = __shfl_sync(0xffffffffu, wbase, 31);
                int off = wbase + inc - cnt;
                #pragma unroll
                for (int j = 0; j < 16; j++) {
                    if ((pm >> j) & 1u) {
                        if (off < CAND_MAX) {
                            cand[off] = xs[j];
                            // element index: chunk (j/4) at stride TPB, lane j%4
                            candIdx[off] = (base + t + (j >> 2) * TPB) * 4 + (j & 3);
                        }
                        off++;
                    }
                }
            }
        }
        __syncthreads();
        n = shn;
        if (n >= k && n <= CAND_MAX) break;
        if (n > CAND_MAX) { loK = fK; fK = fK + ((hiK - fK) >> 1); }
        else              { hiK = fK; fK = loK + ((fK - loK) >> 1); }
        __syncthreads();
    }
    if (n > CAND_MAX) n = CAND_MAX;

    // ---- Row max (fused: reduce per-thread running max of taken elements) ----
    float M = blk_reduce_max(mx, redTmp);

    // ---- Exact top-k threshold: 12/12/8 count radix ----
    float target = (float)k;
    __syncthreads();
    for (int i = t; i < 4096; i += TPB) histbuf[i] = 0.f;
    __syncthreads();
    for (int i = t; i < n; i += TPB)
        atomicAdd(&histbuf[f2ord(cand[i]) >> 20], 1.f);
    CrossRes c1r = find_crossing<4096>(histbuf, target, scanTmp, &shr, &shb, &shc);
    target -= c1r.above;
    unsigned pfx12 = (unsigned)c1r.bin;
    __syncthreads();
    for (int i = t; i < 4096; i += TPB) histbuf[i] = 0.f;
    __syncthreads();
    for (int i = t; i < n; i += TPB) {
        unsigned ou = f2ord(cand[i]);
        if ((ou >> 20) == pfx12) atomicAdd(&histbuf[(ou >> 8) & 4095u], 1.f);
    }
    CrossRes c2r = find_crossing<4096>(histbuf, target, scanTmp, &shr, &shb, &shc);
    target -= c2r.above;
    unsigned pfx24 = (pfx12 << 12) | (unsigned)c2r.bin;
    __syncthreads();
    if (t < 256) histbuf[t] = 0.f;
    __syncthreads();
    for (int i = t; i < n; i += TPB) {
        unsigned ou = f2ord(cand[i]);
        if ((ou >> 8) == pfx24) atomicAdd(&histbuf[ou & 255u], 1.f);
    }
    CrossRes c3r = find_crossing<256>(histbuf, target, scanTmp, &shr, &shb, &shc);
    const unsigned thr_ou = (pfx24 << 8) | (unsigned)c3r.bin;

    // ---- Weighted 12/10/10 descent; Zk and Zf fused into hist totals ----
    float Zk, zf;
    unsigned t_ou;
    {
        __syncthreads();
        for (int i = t; i < 4096; i += TPB) histbuf[i] = 0.f;
        __syncthreads();
        for (int i = t; i < n; i += TPB) {
            float x = cand[i]; unsigned ou = f2ord(x);
            if (ou >= thr_ou) atomicAdd(&histbuf[ou >> 20], __expf(x - M));
        }
        Zk = hist_total<4096>(histbuf, redTmp);
        float T = p * Zk;
        CrossRes w1 = find_crossing<4096>(histbuf, T, scanTmp, &shr, &shb, &shc);
        if (!w1.found) {
            t_ou = thr_ou; zf = Zk;
        } else {
            float ab1 = w1.above;
            unsigned wc1 = (unsigned)w1.bin;
            __syncthreads();
            if (t < 1024) histbuf[t] = 0.f;
            __syncthreads();
            for (int i = t; i < n; i += TPB) {
                float x = cand[i]; unsigned ou = f2ord(x);
                if (ou >= thr_ou && (ou >> 20) == wc1)
                    atomicAdd(&histbuf[(ou >> 10) & 1023u], __expf(x - M));
            }
            float tot2 = hist_total<1024>(histbuf, redTmp);
            CrossRes w2 = find_crossing<1024>(histbuf, T - ab1, scanTmp, &shr, &shb, &shc);
            if (!w2.found) {
                t_ou = wc1 << 20; zf = ab1 + tot2;
            } else {
                float ab2 = w2.above;
                unsigned pw = (wc1 << 10) | (unsigned)w2.bin;
                __syncthreads();
                if (t < 1024) histbuf[t] = 0.f;
                __syncthreads();
                for (int i = t; i < n; i += TPB) {
                    float x = cand[i]; unsigned ou = f2ord(x);
                    if (ou >= thr_ou && (ou >> 10) == pw)
                        atomicAdd(&histbuf[ou & 1023u], __expf(x - M));
                }
                float tot3 = hist_total<1024>(histbuf, redTmp);
                CrossRes w3 = find_crossing<1024>(histbuf, T - ab1 - ab2,
                                                  scanTmp, &shr, &shb, &shc);
                if (!w3.found) {
                    t_ou = pw << 10; zf = ab1 + ab2 + tot3;
                } else {
                    t_ou = (pw << 10) | (unsigned)w3.bin;
                    zf = ab1 + ab2 + w3.above + histbuf[w3.bin];
                }
            }
        }
    }
    if (t_ou <= thr_ou) zf = Zk;                 // f_ou = thr_ou -> kept = top-k set
    const unsigned f_ou = (t_ou > thr_ou) ? t_ou : thr_ou;
    const float ford = ord2f_floor(f_ou);
    const float invZ = 1.0f / zf;

    // ---- Sparse scatter of kept probs + fused Gumbel-max argmax ----
    float bv = -1.f; int bi = 0x7fffffff;
    for (int i = t; i < n; i += TPB) {
        float x = cand[i];
        if (x >= ford) {
            int idx = candIdx[i];
            float prob = __expf(x - M) * invZ;
            pro[idx] = prob;
            float ratio = prob / (-__logf(qr[idx]));
            if (ratio > bv || (ratio == bv && idx < bi)) { bv = ratio; bi = idx; }
        }
    }
    #pragma unroll
    for (int o = 16; o; o >>= 1) {
        float ov = __shfl_down_sync(0xffffffffu, bv, o);
        int   oi = __shfl_down_sync(0xffffffffu, bi, o);
        if (ov > bv || (ov == bv && oi < bi)) { bv = ov; bi = oi; }
    }
    if (lane == 0) { argV[warp] = bv; argI[warp] = bi; }
    __syncthreads();
    if (warp == 0) {
        bv = argV[lane]; bi = argI[lane];
        #pragma unroll
        for (int o = 16; o; o >>= 1) {
            float ov = __shfl_down_sync(0xffffffffu, bv, o);
            int   oi = __shfl_down_sync(0xffffffffu, bi, o);
            if (ov > bv || (ov == bv && oi < bi)) { bv = ov; bi = oi; }
        }
        if (lane == 0) out_ids[row] = (float)bi;
    }
}

extern "C" void kernel_launch(void* const* d_in, const int* in_sizes, int n_in,
                              void* d_out, int out_size) {
    const float* logits = (const float*)d_in[0];
    const int*   k      = (const int*)  d_in[1];
    const float* p      = (const float*)d_in[2];
    const float* q      = (const float*)d_in[3];
    float* out = (float*)d_out;
    float* out_ids   = out;
    float* out_probs = out + BB;
    topk_topp_sample_kernel<<<BB, TPB>>>(logits, k, p, q, out_ids, out_probs);
}

// round 14
// speedup vs baseline: 1.9192x; 1.9192x over previous
#include <cuda_runtime.h>
#include <math.h>

#define BB   128
#define VV   128000
#define NV4  (VV/4)
#define TPB  1024
#define CAND_MAX 3968

// monotonic float -> ordered uint32
__device__ __forceinline__ unsigned f2ord(float f) {
    unsigned u = __float_as_uint(f);
    return (u & 0x80000000u) ? ~u : (u | 0x80000000u);
}
// inverse (floor decode); NaN-zone keys self-correct the bisection
__device__ __forceinline__ float ord2f_floor(unsigned o) {
    if (o <= 0x007FFFFFu) return -__int_as_float(0x7f800000); // -inf: take all
    return (o & 0x80000000u) ? __uint_as_float(o ^ 0x80000000u)
                             : __uint_as_float(~o);
}
__device__ __forceinline__ unsigned shr32(unsigned x, int s) {
    return (s >= 32) ? 0u : (x >> s);
}
__device__ __forceinline__ unsigned shl32(unsigned x, int s) {
    return (s >= 32) ? 0u : (x << s);
}

__device__ float blk_excl_scan(float v, float* tmp) {
    __syncthreads();
    int lane = threadIdx.x & 31, w = threadIdx.x >> 5;
    float x = v;
    #pragma unroll
    for (int o = 1; o < 32; o <<= 1) {
        float y = __shfl_up_sync(0xffffffffu, x, o);
        if (lane >= o) x += y;
    }
    if (lane == 31) tmp[w] = x;
    __syncthreads();
    if (w == 0) {
        float s = tmp[lane];
        #pragma unroll
        for (int o = 1; o < 32; o <<= 1) {
            float y = __shfl_up_sync(0xffffffffu, s, o);
            if (lane >= o) s += y;
        }
        tmp[lane] = s;
    }
    __syncthreads();
    float pre = (w > 0) ? tmp[w - 1] : 0.0f;
    return pre + x - v;
    // NOTE: after return, tmp[31] == grand total of all v
}

__device__ float blk_reduce_max(float v, float* tmp) {
    __syncthreads();
    int lane = threadIdx.x & 31, w = threadIdx.x >> 5;
    #pragma unroll
    for (int o = 16; o; o >>= 1) v = fmaxf(v, __shfl_xor_sync(0xffffffffu, v, o));
    if (lane == 0) tmp[w] = v;
    __syncthreads();
    if (w == 0) {
        float x = tmp[lane];
        #pragma unroll
        for (int o = 16; o; o >>= 1) x = fmaxf(x, __shfl_xor_sync(0xffffffffu, x, o));
        if (lane == 0) tmp[0] = x;
    }
    __syncthreads();
    return tmp[0];
}

struct Cross2 { int bin; float above; float total; float tgt; bool found; };

// 1024-bin descending crossing (bpt=1). Finds bin c with
// cumAbove < tgt <= cumAbove + w[c]; tgt = tv (or tv*total when isFrac).
// Deterministic tie-break via atomicMin on rank. Hist total comes free.
__device__ Cross2 crossing1024(const float* wgt, float tv, bool isFrac,
                               float* scanTmp, int* sh_r, int* sh_b, float* sh_c) {
    __syncthreads();                        // hist writes visible
    int t = threadIdx.x;
    float s = wgt[1023 - t];                // rank t = t-th from top
    float P = blk_excl_scan(s, scanTmp);    // cum weight strictly above
    float total = scanTmp[31];
    float tgt = isFrac ? tv * total : tv;
    if (t == 0) *sh_r = 0x7fffffff;
    __syncthreads();
    bool hit = (P < tgt && P + s >= tgt);
    if (hit) atomicMin(sh_r, t);
    __syncthreads();
    int fr = *sh_r;
    if (hit && t == fr) { *sh_b = 1023 - t; *sh_c = P; }
    __syncthreads();
    Cross2 r;
    r.found = (fr != 0x7fffffff);
    r.bin   = r.found ? *sh_b : 0;
    r.above = r.found ? *sh_c : 0.f;
    r.total = total;
    r.tgt   = tgt;
    return r;
}

__global__ void __launch_bounds__(TPB, 1)
topk_topp_sample_kernel(const float* __restrict__ logits,
                        const int*   __restrict__ karr,
                        const float* __restrict__ parr,
                        const float* __restrict__ qarr,
                        float* __restrict__ out_ids,
                        float* __restrict__ out_probs)
{
    __shared__ float cand[CAND_MAX];      // 15.5 KB
    __shared__ int   candIdx[CAND_MAX];   // 15.5 KB
    __shared__ float histbuf[1024];       // 4 KB
    __shared__ float scanTmp[32];
    __shared__ float redTmp[32];
    __shared__ int   shr; __shared__ int shb; __shared__ float shc;
    __shared__ int   shn;
    __shared__ float argV[32]; __shared__ int argI[32];

    const int row = blockIdx.x;
    const int t = threadIdx.x;
    const int lane = t & 31, warp = t >> 5;
    const float* lg = logits + (long long)row * VV;
    const float* qr = qarr   + (long long)row * VV;
    float* pro = out_probs + (long long)row * VV;
    const int   k = karr[row];
    const float p = parr[row];

    const float4* lg4 = reinterpret_cast<const float4*>(lg);
    float4* pr4 = reinterpret_cast<float4*>(pro);

    // ---- Zero-fill probs first: fire-and-forget stores drain over the kernel ----
    {
        const float4 z4 = make_float4(0.f, 0.f, 0.f, 0.f);
        int i = t;
        #pragma unroll 4
        for (; i < NV4; i += TPB) pr4[i] = z4;
    }

    // ---- Phase A: ILP-4 compaction, warp-scan offsets, fused row max ----
    const float NEG = -__int_as_float(0x7f800000);   // -inf sentinel (never taken)
    unsigned loK = 0u, hiK = 0xFFFFFFFFu, fK = 0xC0000000u;  // f2ord(2.0f)
    int n = 0;
    float mx;
    for (int iter = 0; iter < 20; iter++) {
        if (t == 0) shn = 0;
        mx = -3.4e38f;
        __syncthreads();
        const float ffloor = ord2f_floor(fK);
        for (int base = 0; base < NV4; base += 4 * TPB) {
            int i0 = base + t, i1 = i0 + TPB, i2 = i1 + TPB, i3 = i2 + TPB;
            float4 v0 = (i0 < NV4) ? lg4[i0] : make_float4(NEG, NEG, NEG, NEG);
            float4 v1 = (i1 < NV4) ? lg4[i1] : make_float4(NEG, NEG, NEG, NEG);
            float4 v2 = (i2 < NV4) ? lg4[i2] : make_float4(NEG, NEG, NEG, NEG);
            float4 v3 = (i3 < NV4) ? lg4[i3] : make_float4(NEG, NEG, NEG, NEG);
            float xs[16] = { v0.x, v0.y, v0.z, v0.w,  v1.x, v1.y, v1.z, v1.w,
                             v2.x, v2.y, v2.z, v2.w,  v3.x, v3.y, v3.z, v3.w };
            unsigned pm = 0;
            int cnt = 0;
            #pragma unroll
            for (int j = 0; j < 16; j++) {
                bool tk = (xs[j] >= ffloor);
                pm |= (unsigned)tk << j;
                cnt += (int)tk;
                if (tk) mx = fmaxf(mx, xs[j]);
            }
            int inc = cnt;
            #pragma unroll
            for (int o = 1; o < 32; o <<= 1) {
                int y = __shfl_up_sync(0xffffffffu, inc, o);
                if (lane >= o) inc += y;
            }
            int wtot = __shfl_sync(0xffffffffu, inc, 31);
            if (wtot) {
                int wbase = 0;
                if (lane == 31) wbase = atomicAdd(&shn, wtot);
                wbase = __shfl_sync(0xffffffffu, wbase, 31);
                int off = wbase + inc - cnt;
                #pragma unroll
                for (int j = 0; j < 16; j++) {
                    if ((pm >> j) & 1u) {
                        if (off < CAND_MAX) {
                            cand[off] = xs[j];
                            candIdx[off] = (base + t + (j >> 2) * TPB) * 4 + (j & 3);
                        }
                        off++;
                    }
                }
            }
        }
        __syncthreads();
        n = shn;
        if (n >= k && n <= CAND_MAX) break;
        if (n > CAND_MAX) { loK = fK; fK = fK + ((hiK - fK) >> 1); }
        else              { hiK = fK; fK = loK + ((fK - loK) >> 1); }
        __syncthreads();
    }
    if (n > CAND_MAX) n = CAND_MAX;

    // ---- Row max ----
    float M = blk_reduce_max(mx, redTmp);
    const unsigned maxKey = f2ord(M);

    // ---- Exact top-k threshold: exact-prefix 10-bit radix descent ----
    unsigned thr_ou = maxKey;
    {
        unsigned diff = maxKey ^ fK;                 // candidates span [fK, maxKey]
        int hb = (diff == 0u) ? 0 : (31 - __clz(diff));
        int sh = hb + 1;                             // all cands share bits [31..sh]
        unsigned prefix = shr32(maxKey, sh);
        float tgt = (float)k;
        while (sh > 0) {
            int nsh = (sh > 10) ? sh - 10 : 0;
            int d = sh - nsh;                        // window width, 1..10
            histbuf[t] = 0.f;
            __syncthreads();
            for (int i = t; i < n; i += TPB) {
                unsigned ou = f2ord(cand[i]);
                if (shr32(ou, sh) == prefix)         // FULL resolved prefix test
                    atomicAdd(&histbuf[(ou >> nsh) & 1023u], 1.f);
            }
            Cross2 cr = crossing1024(histbuf, tgt, false, scanTmp, &shr, &shb, &shc);
            if (!cr.found) {                          // defensive
                thr_ou = shl32(prefix, sh);
                break;
            }
            tgt = cr.tgt - cr.above;
            prefix = ((prefix >> (10 - d)) << 10) | (unsigned)cr.bin;  // = ou>>nsh
            sh = nsh;
            if (sh == 0) thr_ou = prefix;
        }
    }

    // ---- Weighted exact-prefix descent for top-p cutoff; Zk/Zf fused ----
    float Zk = 0.f, zf = 0.f;
    unsigned t_ou;
    {
        unsigned diff = maxKey ^ thr_ou;             // kept span [thr_ou, maxKey]
        int hbw = (diff == 0u) ? 0 : (31 - __clz(diff));
        int sh = hbw + 1;
        unsigned prefix = shr32(maxKey, sh);
        float zfacc = 0.f, tgt = 0.f;
        bool first = true;
        while (1) {
            int nsh = (sh > 10) ? sh - 10 : 0;
            int d = sh - nsh;
            histbuf[t] = 0.f;
            __syncthreads();
            for (int i = t; i < n; i += TPB) {
                float x = cand[i];
                unsigned ou = f2ord(x);
                if (ou >= thr_ou && shr32(ou, sh) == prefix)
                    atomicAdd(&histbuf[(ou >> nsh) & 1023u], __expf(x - M));
            }
            Cross2 cr = crossing1024(histbuf, first ? p : tgt, first,
                                     scanTmp, &shr, &shb, &shc);
            if (first) { Zk = cr.total; first = false; }
            if (!cr.found) {                          // keep whole current window
                t_ou = shl32(prefix, sh);
                zf = zfacc + cr.total;
                break;
            }
            zfacc += cr.above;
            prefix = ((prefix >> (10 - d)) << 10) | (unsigned)cr.bin;
            if (nsh == 0) {
                t_ou = prefix;
                zf = zfacc + histbuf[cr.bin];         // hist intact after crossing
                break;
            }
            tgt = cr.tgt - cr.above;
            sh = nsh;
        }
    }
    if (t_ou <= thr_ou) zf = Zk;                 // kept set = full top-k set
    const unsigned f_ou = (t_ou > thr_ou) ? t_ou : thr_ou;
    const float ford = ord2f_floor(f_ou);
    const float invZ = 1.0f / zf;

    // ---- Sparse scatter of kept probs + fused Gumbel-max argmax ----
    float bv = -1.f; int bi = 0x7fffffff;
    for (int i = t; i < n; i += TPB) {
        float x = cand[i];
        if (x >= ford) {
            int idx = candIdx[i];
            float prob = __expf(x - M) * invZ;
            pro[idx] = prob;
            float ratio = prob / (-__logf(qr[idx]));
            if (ratio > bv || (ratio == bv && idx < bi)) { bv = ratio; bi = idx; }
        }
    }
    #pragma unroll
    for (int o = 16; o; o >>= 1) {
        float ov = __shfl_down_sync(0xffffffffu, bv, o);
        int   oi = __shfl_down_sync(0xffffffffu, bi, o);
        if (ov > bv || (ov == bv && oi < bi)) { bv = ov; bi = oi; }
    }
    if (lane == 0) { argV[warp] = bv; argI[warp] = bi; }
    __syncthreads();
    if (warp == 0) {
        bv = argV[lane]; bi = argI[lane];
        #pragma unroll
        for (int o = 16; o; o >>= 1) {
            float ov = __shfl_down_sync(0xffffffffu, bv, o);
            int   oi = __shfl_down_sync(0xffffffffu, bi, o);
            if (ov > bv || (ov == bv && oi < bi)) { bv = ov; bi = oi; }
        }
        if (lane == 0) out_ids[row] = (float)bi;
    }
}

extern "C" void kernel_launch(void* const* d_in, const int* in_sizes, int n_in,
                              void* d_out, int out_size) {
    const float* logits = (const float*)d_in[0];
    const int*   k      = (const int*)  d_in[1];
    const float* p      = (const float*)d_in[2];
    const float* q      = (const float*)d_in[3];
    float* out = (float*)d_out;
    float* out_ids   = out;
    float* out_probs = out + BB;
    topk_topp_sample_kernel<<<BB, TPB>>>(logits, k, p, q, out_ids, out_probs);
}

// round 15
// speedup vs baseline: 2.1848x; 1.1384x over previous
#include <cuda_runtime.h>
#include <math.h>

#define BB   128
#define VV   128000
#define NV4  (VV/4)
#define TPB  1024
#define CAND_MAX 3968

// monotonic float -> ordered uint32
__device__ __forceinline__ unsigned f2ord(float f) {
    unsigned u = __float_as_uint(f);
    return (u & 0x80000000u) ? ~u : (u | 0x80000000u);
}
// inverse (floor decode); NaN-zone keys self-correct the bisection
__device__ __forceinline__ float ord2f_floor(unsigned o) {
    if (o <= 0x007FFFFFu) return -__int_as_float(0x7f800000); // -inf: take all
    return (o & 0x80000000u) ? __uint_as_float(o ^ 0x80000000u)
                             : __uint_as_float(~o);
}
__device__ __forceinline__ unsigned shr32(unsigned x, int s) {
    return (s >= 32) ? 0u : (x >> s);
}
__device__ __forceinline__ unsigned shl32(unsigned x, int s) {
    return (s >= 32) ? 0u : (x << s);
}

__device__ float blk_excl_scan(float v, float* tmp) {
    __syncthreads();
    int lane = threadIdx.x & 31, w = threadIdx.x >> 5;
    float x = v;
    #pragma unroll
    for (int o = 1; o < 32; o <<= 1) {
        float y = __shfl_up_sync(0xffffffffu, x, o);
        if (lane >= o) x += y;
    }
    if (lane == 31) tmp[w] = x;
    __syncthreads();
    if (w == 0) {
        float s = tmp[lane];
        #pragma unroll
        for (int o = 1; o < 32; o <<= 1) {
            float y = __shfl_up_sync(0xffffffffu, s, o);
            if (lane >= o) s += y;
        }
        tmp[lane] = s;
    }
    __syncthreads();
    float pre = (w > 0) ? tmp[w - 1] : 0.0f;
    return pre + x - v;
    // NOTE: after return, tmp[31] == grand total of all v
}

__device__ float blk_reduce_max(float v, float* tmp) {
    __syncthreads();
    int lane = threadIdx.x & 31, w = threadIdx.x >> 5;
    #pragma unroll
    for (int o = 16; o; o >>= 1) v = fmaxf(v, __shfl_xor_sync(0xffffffffu, v, o));
    if (lane == 0) tmp[w] = v;
    __syncthreads();
    if (w == 0) {
        float x = tmp[lane];
        #pragma unroll
        for (int o = 16; o; o >>= 1) x = fmaxf(x, __shfl_xor_sync(0xffffffffu, x, o));
        if (lane == 0) tmp[0] = x;
    }
    __syncthreads();
    return tmp[0];
}

struct Cross2 { int bin; float above; float total; float tgt; bool found; };

// 1024-bin descending crossing (bpt=1). Finds bin c with
// cumAbove < tgt <= cumAbove + w[c]; tgt = tv (or tv*total when isFrac).
__device__ Cross2 crossing1024(const float* wgt, float tv, bool isFrac,
                               float* scanTmp, int* sh_r, int* sh_b, float* sh_c) {
    __syncthreads();                        // hist writes visible
    int t = threadIdx.x;
    float s = wgt[1023 - t];                // rank t = t-th from top
    float P = blk_excl_scan(s, scanTmp);    // cum weight strictly above
    float total = scanTmp[31];
    float tgt = isFrac ? tv * total : tv;
    if (t == 0) *sh_r = 0x7fffffff;
    __syncthreads();
    bool hit = (P < tgt && P + s >= tgt);
    if (hit) atomicMin(sh_r, t);
    __syncthreads();
    int fr = *sh_r;
    if (hit && t == fr) { *sh_b = 1023 - t; *sh_c = P; }
    __syncthreads();
    Cross2 r;
    r.found = (fr != 0x7fffffff);
    r.bin   = r.found ? *sh_b : 0;
    r.above = r.found ? *sh_c : 0.f;
    r.total = total;
    r.tgt   = tgt;
    return r;
}

__global__ void __launch_bounds__(TPB, 1)
topk_topp_sample_kernel(const float* __restrict__ logits,
                        const int*   __restrict__ karr,
                        const float* __restrict__ parr,
                        const float* __restrict__ qarr,
                        float* __restrict__ out_ids,
                        float* __restrict__ out_probs)
{
    __shared__ float cand[CAND_MAX];      // 15.5 KB
    __shared__ int   candIdx[CAND_MAX];   // 15.5 KB
    __shared__ float histbuf[1024];       // 4 KB
    __shared__ float scanTmp[32];
    __shared__ float redTmp[32];
    __shared__ int   shr; __shared__ int shb; __shared__ float shc;
    __shared__ int   shn;
    __shared__ float argV[32]; __shared__ int argI[32];

    const int row = blockIdx.x;
    const int t = threadIdx.x;
    const int lane = t & 31, warp = t >> 5;
    const float* lg = logits + (long long)row * VV;
    const float* qr = qarr   + (long long)row * VV;
    float* pro = out_probs + (long long)row * VV;
    const int   k = karr[row];
    const float p = parr[row];

    const float4* lg4 = reinterpret_cast<const float4*>(lg);
    float4* pr4 = reinterpret_cast<float4*>(pro);

    // ---- Phase A: ILP-4 compaction + fused zero-fill + hierarchical test ----
    const float NEG = -__int_as_float(0x7f800000);   // -inf sentinel (never taken)
    const float4 z4 = make_float4(0.f, 0.f, 0.f, 0.f);
    unsigned loK = 0u, hiK = 0xFFFFFFFFu, fK = 0xC0000000u;  // f2ord(2.0f)
    int n = 0;
    float mx;
    bool doZero = true;
    for (int iter = 0; iter < 20; iter++) {
        if (t == 0) shn = 0;
        mx = -3.4e38f;
        __syncthreads();
        const float ffloor = ord2f_floor(fK);
        for (int base = 0; base < NV4; base += 4 * TPB) {
            int i0 = base + t, i1 = i0 + TPB, i2 = i1 + TPB, i3 = i2 + TPB;
            float4 v0 = (i0 < NV4) ? lg4[i0] : make_float4(NEG, NEG, NEG, NEG);
            float4 v1 = (i1 < NV4) ? lg4[i1] : make_float4(NEG, NEG, NEG, NEG);
            float4 v2 = (i2 < NV4) ? lg4[i2] : make_float4(NEG, NEG, NEG, NEG);
            float4 v3 = (i3 < NV4) ? lg4[i3] : make_float4(NEG, NEG, NEG, NEG);
            if (doZero) {     // interleave output zeroing with the read stream
                if (i0 < NV4) pr4[i0] = z4;
                if (i1 < NV4) pr4[i1] = z4;
                if (i2 < NV4) pr4[i2] = z4;
                if (i3 < NV4) pr4[i3] = z4;
            }
            // per-float4 maxes (also feeds row max: global max = max over all)
            float m0 = fmaxf(fmaxf(v0.x, v0.y), fmaxf(v0.z, v0.w));
            float m1 = fmaxf(fmaxf(v1.x, v1.y), fmaxf(v1.z, v1.w));
            float m2 = fmaxf(fmaxf(v2.x, v2.y), fmaxf(v2.z, v2.w));
            float m3 = fmaxf(fmaxf(v3.x, v3.y), fmaxf(v3.z, v3.w));
            mx = fmaxf(mx, fmaxf(fmaxf(m0, m1), fmaxf(m2, m3)));
            unsigned pm = 0;
            if (m0 >= ffloor)
                pm |= (unsigned)(v0.x >= ffloor)       | ((unsigned)(v0.y >= ffloor) << 1)
                    | ((unsigned)(v0.z >= ffloor) << 2) | ((unsigned)(v0.w >= ffloor) << 3);
            if (m1 >= ffloor)
                pm |= ((unsigned)(v1.x >= ffloor) << 4) | ((unsigned)(v1.y >= ffloor) << 5)
                    | ((unsigned)(v1.z >= ffloor) << 6) | ((unsigned)(v1.w >= ffloor) << 7);
            if (m2 >= ffloor)
                pm |= ((unsigned)(v2.x >= ffloor) << 8)  | ((unsigned)(v2.y >= ffloor) << 9)
                    | ((unsigned)(v2.z >= ffloor) << 10) | ((unsigned)(v2.w >= ffloor) << 11);
            if (m3 >= ffloor)
                pm |= ((unsigned)(v3.x >= ffloor) << 12) | ((unsigned)(v3.y >= ffloor) << 13)
                    | ((unsigned)(v3.z >= ffloor) << 14) | ((unsigned)(v3.w >= ffloor) << 15);
            int cnt = __popc(pm);
            int inc = cnt;
            #pragma unroll
            for (int o = 1; o < 32; o <<= 1) {
                int y = __shfl_up_sync(0xffffffffu, inc, o);
                if (lane >= o) inc += y;
            }
            int wtot = __shfl_sync(0xffffffffu, inc, 31);
            if (wtot) {
                int wbase = 0;
                if (lane == 31) wbase = atomicAdd(&shn, wtot);
                wbase = __shfl_sync(0xffffffffu, wbase, 31);
                int off = wbase + inc - cnt;
                float xs[16] = { v0.x, v0.y, v0.z, v0.w,  v1.x, v1.y, v1.z, v1.w,
                                 v2.x, v2.y, v2.z, v2.w,  v3.x, v3.y, v3.z, v3.w };
                #pragma unroll
                for (int j = 0; j < 16; j++) {
                    if ((pm >> j) & 1u) {
                        if (off < CAND_MAX) {
                            cand[off] = xs[j];
                            candIdx[off] = (base + t + (j >> 2) * TPB) * 4 + (j & 3);
                        }
                        off++;
                    }
                }
            }
        }
        doZero = false;
        __syncthreads();
        n = shn;
        if (n >= k && n <= CAND_MAX) break;
        if (n > CAND_MAX) { loK = fK; fK = fK + ((hiK - fK) >> 1); }
        else              { hiK = fK; fK = loK + ((fK - loK) >> 1); }
        __syncthreads();
    }
    if (n > CAND_MAX) n = CAND_MAX;

    // ---- Row max ----
    float M = blk_reduce_max(mx, redTmp);
    const unsigned maxKey = f2ord(M);

    // ---- Exact top-k threshold: exact-prefix 10-bit radix descent ----
    unsigned thr_ou = maxKey;
    {
        unsigned diff = maxKey ^ fK;                 // candidates span [fK, maxKey]
        int hb = (diff == 0u) ? 0 : (31 - __clz(diff));
        int sh = hb + 1;                             // all cands share bits [31..sh]
        unsigned prefix = shr32(maxKey, sh);
        float tgt = (float)k;
        while (sh > 0) {
            int nsh = (sh > 10) ? sh - 10 : 0;
            int d = sh - nsh;                        // window width, 1..10
            histbuf[t] = 0.f;
            __syncthreads();
            for (int i = t; i < n; i += TPB) {
                unsigned ou = f2ord(cand[i]);
                if (shr32(ou, sh) == prefix)         // FULL resolved prefix test
                    atomicAdd(&histbuf[(ou >> nsh) & 1023u], 1.f);
            }
            Cross2 cr = crossing1024(histbuf, tgt, false, scanTmp, &shr, &shb, &shc);
            if (!cr.found) {                          // defensive
                thr_ou = shl32(prefix, sh);
                break;
            }
            tgt = cr.tgt - cr.above;
            prefix = ((prefix >> (10 - d)) << 10) | (unsigned)cr.bin;  // = ou>>nsh
            sh = nsh;
            if (sh == 0) thr_ou = prefix;
        }
    }

    // ---- Weighted exact-prefix descent for top-p cutoff; Zk/Zf fused ----
    float Zk = 0.f, zf = 0.f;
    unsigned t_ou;
    {
        unsigned diff = maxKey ^ thr_ou;             // kept span [thr_ou, maxKey]
        int hbw = (diff == 0u) ? 0 : (31 - __clz(diff));
        int sh = hbw + 1;
        unsigned prefix = shr32(maxKey, sh);
        float zfacc = 0.f, tgt = 0.f;
        bool first = true;
        while (1) {
            int nsh = (sh > 10) ? sh - 10 : 0;
            int d = sh - nsh;
            histbuf[t] = 0.f;
            __syncthreads();
            for (int i = t; i < n; i += TPB) {
                float x = cand[i];
                unsigned ou = f2ord(x);
                if (ou >= thr_ou && shr32(ou, sh) == prefix)
                    atomicAdd(&histbuf[(ou >> nsh) & 1023u], __expf(x - M));
            }
            Cross2 cr = crossing1024(histbuf, first ? p : tgt, first,
                                     scanTmp, &shr, &shb, &shc);
            if (first) { Zk = cr.total; first = false; }
            if (!cr.found) {                          // keep whole current window
                t_ou = shl32(prefix, sh);
                zf = zfacc + cr.total;
                break;
            }
            zfacc += cr.above;
            prefix = ((prefix >> (10 - d)) << 10) | (unsigned)cr.bin;
            if (nsh == 0) {
                t_ou = prefix;
                zf = zfacc + histbuf[cr.bin];         // hist intact after crossing
                break;
            }
            tgt = cr.tgt - cr.above;
            sh = nsh;
        }
    }
    if (t_ou <= thr_ou) zf = Zk;                 // kept set = full top-k set
    const unsigned f_ou = (t_ou > thr_ou) ? t_ou : thr_ou;
    const float ford = ord2f_floor(f_ou);
    const float invZ = 1.0f / zf;

    // ---- Sparse scatter of kept probs + fused Gumbel-max argmax ----
    // (__syncthreads since zero stores -> block-scope store ordering holds)
    float bv = -1.f; int bi = 0x7fffffff;
    for (int i = t; i < n; i += TPB) {
        float x = cand[i];
        if (x >= ford) {
            int idx = candIdx[i];
            float prob = __expf(x - M) * invZ;
            pro[idx] = prob;
            float ratio = prob / (-__logf(qr[idx]));
            if (ratio > bv || (ratio == bv && idx < bi)) { bv = ratio; bi = idx; }
        }
    }
    #pragma unroll
    for (int o = 16; o; o >>= 1) {
        float ov = __shfl_down_sync(0xffffffffu, bv, o);
        int   oi = __shfl_down_sync(0xffffffffu, bi, o);
        if (ov > bv || (ov == bv && oi < bi)) { bv = ov; bi = oi; }
    }
    if (lane == 0) { argV[warp] = bv; argI[warp] = bi; }
    __syncthreads();
    if (warp == 0) {
        bv = argV[lane]; bi = argI[lane];
        #pragma unroll
        for (int o = 16; o; o >>= 1) {
            float ov = __shfl_down_sync(0xffffffffu, bv, o);
            int   oi = __shfl_down_sync(0xffffffffu, bi, o);
            if (ov > bv || (ov == bv && oi < bi)) { bv = ov; bi = oi; }
        }
        if (lane == 0) out_ids[row] = (float)bi;
    }
}

extern "C" void kernel_launch(void* const* d_in, const int* in_sizes, int n_in,
                              void* d_out, int out_size) {
    const float* logits = (const float*)d_in[0];
    const int*   k      = (const int*)  d_in[1];
    const float* p      = (const float*)d_in[2];
    const float* q      = (const float*)d_in[3];
    float* out = (float*)d_out;
    float* out_ids   = out;
    float* out_probs = out + BB;
    topk_topp_sample_kernel<<<BB, TPB>>>(logits, k, p, q, out_ids, out_probs);
}